// round 1
// baseline (speedup 1.0000x reference)
#include <cuda_runtime.h>
#include <cstdint>
#include <math.h>

// Problem constants (fixed shapes for CompatibleLearningLoss)
constexpr int NROW = 128;    // N (batch)
constexpr int DDIM = 512;    // D (embed dim)
constexpr int CDIM = 8192;   // C (logit dim)
constexpr int NQ   = 32768;  // Q (queue length), power of 2

// ---------------- device scratch (no runtime allocation allowed) ----------------
__device__ __align__(16) float g_s1[(size_t)NROW * NQ];   // l1 scores [N,Q]
__device__ __align__(16) float g_s2[(size_t)NROW * NQ];   // l2 scores [N,Q]
__device__ __align__(16) float g_new_e[NROW * DDIM];      // normalized new_embeds
__device__ int   g_qlab[NQ];                              // updated queue labels
__device__ float g_terms[2 * NROW];                       // per-row mean_log_prob_pos

// ---------------- kernel 0: row-normalize new_embeds ----------------
__global__ void normalize_rows(const float* __restrict__ x) {
    int i = blockIdx.x;                 // row
    int tid = threadIdx.x;              // 128 threads
    const float* xr = x + (size_t)i * DDIM;
    float s = 0.f;
    for (int d = tid; d < DDIM; d += 128) {
        float v = xr[d];
        s += v * v;
    }
    // warp reduce
    for (int o = 16; o; o >>= 1) s += __shfl_down_sync(0xffffffffu, s, o);
    __shared__ float sh[4];
    if ((tid & 31) == 0) sh[tid >> 5] = s;
    __syncthreads();
    __shared__ float inv;
    if (tid == 0) {
        float tot = sh[0] + sh[1] + sh[2] + sh[3];
        float nrm = sqrtf(tot);
        inv = 1.0f / fmaxf(nrm, 1e-12f);
    }
    __syncthreads();
    float iv = inv;
    for (int d = tid; d < DDIM; d += 128)
        g_new_e[i * DDIM + d] = xr[d] * iv;
}

// ---------------- kernel 1: build updated queue labels ----------------
__global__ void build_qlab(const int* __restrict__ ql, const int* __restrict__ labels,
                           const int* __restrict__ hdrp) {
    int j = blockIdx.x * blockDim.x + threadIdx.x;
    if (j < NQ) {
        int hdr = *hdrp;
        int r = (j - hdr) & (NQ - 1);   // power-of-2 modulo, safe for negatives
        g_qlab[j] = (r < NROW) ? labels[r] : ql[j];
    }
}

// ---------------- kernel 2: tiled fp32 GEMM: out[m, j] = A[m,:] . Brow(j) ----------------
// A: [128 x K] row-major. B rows redirected: row j -> old rows if (j-header)%Q < 128.
__global__ __launch_bounds__(256) void gemm_scores(
    const float* __restrict__ A,
    const float* __restrict__ Bq,      // queue matrix [NQ x K]
    const float* __restrict__ Bold,    // replacement rows [128 x K]
    const int* __restrict__ hdrp,
    float* __restrict__ out,           // [128 x NQ]
    int K)
{
    constexpr int BM = 128, BN = 64, BK = 16;
    __shared__ float As[BK][BM];
    __shared__ float Bs[BK][BN];

    const int hdr = *hdrp;
    const int n0  = blockIdx.x * BN;
    const int tid = threadIdx.x;
    const int tx  = tid & 15;          // 16 columns of threads -> 64 N
    const int ty  = tid >> 4;          // 16 rows of threads    -> 128 M

    float acc[8][4];
#pragma unroll
    for (int u = 0; u < 8; u++)
#pragma unroll
        for (int v = 0; v < 4; v++) acc[u][v] = 0.f;

    // this thread's B-tile load assignment (one float4 per iter)
    const int brow = tid >> 2;         // 0..63
    const int bc4  = tid & 3;          // 0..3
    {
        // hoist row-redirect pointer
    }
    const int j = n0 + brow;
    const int r = (j - hdr) & (NQ - 1);
    const float* bptr = (r < NROW) ? (Bold + (size_t)r * K) : (Bq + (size_t)j * K);

    for (int k0 = 0; k0 < K; k0 += BK) {
        // load A tile: 128x16 = 512 float4, 2 per thread
#pragma unroll
        for (int p = 0; p < 2; p++) {
            int idx = tid + p * 256;
            int m  = idx >> 2;
            int c4 = idx & 3;
            float4 va = *(const float4*)(A + (size_t)m * K + k0 + c4 * 4);
            As[c4 * 4 + 0][m] = va.x;
            As[c4 * 4 + 1][m] = va.y;
            As[c4 * 4 + 2][m] = va.z;
            As[c4 * 4 + 3][m] = va.w;
        }
        // load B tile: 64x16 = 256 float4, 1 per thread
        {
            float4 vb = *(const float4*)(bptr + k0 + bc4 * 4);
            Bs[bc4 * 4 + 0][brow] = vb.x;
            Bs[bc4 * 4 + 1][brow] = vb.y;
            Bs[bc4 * 4 + 2][brow] = vb.z;
            Bs[bc4 * 4 + 3][brow] = vb.w;
        }
        __syncthreads();

#pragma unroll
        for (int k = 0; k < BK; k++) {
            float a[8], b[4];
            *(float4*)(a)     = *(const float4*)&As[k][ty * 8];
            *(float4*)(a + 4) = *(const float4*)&As[k][ty * 8 + 4];
            *(float4*)(b)     = *(const float4*)&Bs[k][tx * 4];
#pragma unroll
            for (int u = 0; u < 8; u++)
#pragma unroll
                for (int v = 0; v < 4; v++)
                    acc[u][v] = fmaf(a[u], b[v], acc[u][v]);
        }
        __syncthreads();
    }

#pragma unroll
    for (int u = 0; u < 8; u++) {
        float4 o;
        o.x = acc[u][0]; o.y = acc[u][1]; o.z = acc[u][2]; o.w = acc[u][3];
        *(float4*)(out + (size_t)(ty * 8 + u) * NQ + n0 + tx * 4) = o;
    }
}

// ---------------- kernel 3: per-row reduction ----------------
// For each row i: logsumexp over both score rows, plus masked sums with on-demand weights.
__global__ __launch_bounds__(256) void row_reduce(
    const float* __restrict__ old_embeds,   // [128 x 512]
    const float* __restrict__ feat_queue,   // [NQ x 512]
    const int*   __restrict__ labels,       // [128]
    const int*   __restrict__ hdrp)
{
    const int i   = blockIdx.x;
    const int tid = threadIdx.x;
    const int lbl = labels[i];
    const int hdr = *hdrp;
    const float* s1r = g_s1 + (size_t)i * NQ;
    const float* s2r = g_s2 + (size_t)i * NQ;
    const float* oei = old_embeds + (size_t)i * DDIM;

    float m1 = -INFINITY, l1 = 0.f;
    float m2 = -INFINITY, l2 = 0.f;
    float sw = 0.f, s1w = 0.f, s2w = 0.f;
    int cnt = 0;

    for (int j = tid; j < NQ; j += 256) {
        float v1 = s1r[j];
        float v2 = s2r[j];
        // online logsumexp
        float nm1 = fmaxf(m1, v1);
        l1 = l1 * expf(m1 - nm1) + expf(v1 - nm1);
        m1 = nm1;
        float nm2 = fmaxf(m2, v2);
        l2 = l2 * expf(m2 - nm2) + expf(v2 - nm2);
        m2 = nm2;
        // masked sums (sparse): weight computed on demand
        if (g_qlab[j] == lbl) {
            int r = (j - hdr) & (NQ - 1);
            const float* frow = (r < NROW) ? (old_embeds + (size_t)r * DDIM)
                                           : (feat_queue + (size_t)j * DDIM);
            float dot = 0.f;
#pragma unroll 8
            for (int d = 0; d < DDIM; d++) dot = fmaf(oei[d], frow[d], dot);
            float w = 0.5f * (dot + 1.0f);
            sw  += w;
            s1w += w * v1;
            s2w += w * v2;
            cnt += 1;
        }
    }

    // warp-level combine
    for (int o = 16; o; o >>= 1) {
        float mo = __shfl_down_sync(0xffffffffu, m1, o);
        float lo = __shfl_down_sync(0xffffffffu, l1, o);
        float nm = fmaxf(m1, mo);
        l1 = l1 * expf(m1 - nm) + lo * expf(mo - nm);
        m1 = nm;
        mo = __shfl_down_sync(0xffffffffu, m2, o);
        lo = __shfl_down_sync(0xffffffffu, l2, o);
        nm = fmaxf(m2, mo);
        l2 = l2 * expf(m2 - nm) + lo * expf(mo - nm);
        m2 = nm;
        sw  += __shfl_down_sync(0xffffffffu, sw, o);
        s1w += __shfl_down_sync(0xffffffffu, s1w, o);
        s2w += __shfl_down_sync(0xffffffffu, s2w, o);
        cnt += __shfl_down_sync(0xffffffffu, cnt, o);
    }

    __shared__ float shm1[8], shl1[8], shm2[8], shl2[8], shsw[8], shs1[8], shs2[8];
    __shared__ int shc[8];
    if ((tid & 31) == 0) {
        int w = tid >> 5;
        shm1[w] = m1; shl1[w] = l1; shm2[w] = m2; shl2[w] = l2;
        shsw[w] = sw; shs1[w] = s1w; shs2[w] = s2w; shc[w] = cnt;
    }
    __syncthreads();
    if (tid == 0) {
        float M1 = shm1[0], L1 = shl1[0];
        float M2 = shm2[0], L2 = shl2[0];
        float SW = shsw[0], S1 = shs1[0], S2 = shs2[0];
        int   CN = shc[0];
        for (int w = 1; w < 8; w++) {
            float nm = fmaxf(M1, shm1[w]);
            L1 = L1 * expf(M1 - nm) + shl1[w] * expf(shm1[w] - nm);
            M1 = nm;
            nm = fmaxf(M2, shm2[w]);
            L2 = L2 * expf(M2 - nm) + shl2[w] * expf(shm2[w] - nm);
            M2 = nm;
            SW += shsw[w]; S1 += shs1[w]; S2 += shs2[w]; CN += shc[w];
        }
        // mean_log_prob_pos = (sum(mask*w*s) - lse * sum(mask*w)) / sum(mask)
        float lse1 = M1 + logf(L1);
        float lse2 = M2 + logf(L2);
        float inv_cnt = 1.0f / (float)CN;   // >=1 guaranteed (self match)
        g_terms[i]         = (S1 - lse1 * SW) * inv_cnt;
        g_terms[NROW + i]  = (S2 - lse2 * SW) * inv_cnt;
    }
}

// ---------------- kernel 4: finalize two losses ----------------
__global__ void finalize(float* __restrict__ out) {
    int tid = threadIdx.x;   // 128 threads
    float t1 = g_terms[tid];
    float t2 = g_terms[NROW + tid];
    for (int o = 16; o; o >>= 1) {
        t1 += __shfl_down_sync(0xffffffffu, t1, o);
        t2 += __shfl_down_sync(0xffffffffu, t2, o);
    }
    __shared__ float sh1[4], sh2[4];
    if ((tid & 31) == 0) { sh1[tid >> 5] = t1; sh2[tid >> 5] = t2; }
    __syncthreads();
    if (tid == 0) {
        float a = sh1[0] + sh1[1] + sh1[2] + sh1[3];
        float b = sh2[0] + sh2[1] + sh2[2] + sh2[3];
        out[0] = -a / (float)NROW;   // l1_loss
        out[1] = -b / (float)NROW;   // l2_loss
    }
}

// ---------------- launch ----------------
extern "C" void kernel_launch(void* const* d_in, const int* in_sizes, int n_in,
                              void* d_out, int out_size) {
    const float* old_embeds   = (const float*)d_in[0];
    const float* old_logits   = (const float*)d_in[1];
    const float* new_embeds   = (const float*)d_in[2];
    const float* new_logits   = (const float*)d_in[3];
    const int*   labels       = (const int*)d_in[4];
    const float* feat_queue   = (const float*)d_in[5];
    const float* logit_queue  = (const float*)d_in[6];
    const int*   queue_labels = (const int*)d_in[7];
    const int*   header       = (const int*)d_in[8];
    float* out = (float*)d_out;

    float *p_new_e = nullptr, *p_s1 = nullptr, *p_s2 = nullptr;
    cudaGetSymbolAddress((void**)&p_new_e, g_new_e);
    cudaGetSymbolAddress((void**)&p_s1, g_s1);
    cudaGetSymbolAddress((void**)&p_s2, g_s2);

    normalize_rows<<<NROW, 128>>>(new_embeds);
    build_qlab<<<NQ / 256, 256>>>(queue_labels, labels, header);

    // l1 scores: new_e [128x512] @ feat_queue(updated).T  -> g_s1
    gemm_scores<<<NQ / 64, 256>>>(p_new_e, feat_queue, old_embeds, header, p_s1, DDIM);
    // l2 scores: new_logits [128x8192] @ logit_queue(updated).T -> g_s2
    gemm_scores<<<NQ / 64, 256>>>(new_logits, logit_queue, old_logits, header, p_s2, CDIM);

    row_reduce<<<NROW, 256>>>(old_embeds, feat_queue, labels, header);
    finalize<<<1, 128>>>(out);
}

// round 3
// speedup vs baseline: 2.6290x; 2.6290x over previous
#include <cuda_runtime.h>
#include <cuda_bf16.h>
#include <cstdint>
#include <math.h>

// Shapes (fixed)
constexpr int NROW = 128;
constexpr int DDIM = 512;
constexpr int CDIM = 8192;
constexpr int NQ   = 32768;

// ---------------- device scratch ----------------
__device__ __align__(16) float g_s1[(size_t)NROW * NQ];
__device__ __align__(16) float g_s2[(size_t)NROW * NQ];
__device__ __align__(16) unsigned short g_a1h[NROW * DDIM];
__device__ __align__(16) unsigned short g_a1l[NROW * DDIM];
__device__ __align__(16) unsigned short g_a2h[NROW * CDIM];
__device__ __align__(16) unsigned short g_a2l[NROW * CDIM];
__device__ int   g_qlab[NQ];
__device__ float g_terms[2 * NROW];

// ---------------- small helpers ----------------
__device__ __forceinline__ uint32_t smem_u32(const void* p) {
    uint32_t a;
    asm("{ .reg .u64 t; cvta.to.shared.u64 t, %1; cvt.u32.u64 %0, t; }" : "=r"(a) : "l"(p));
    return a;
}
__device__ __forceinline__ void ldm4(uint32_t* r, uint32_t addr) {
    asm volatile("ldmatrix.sync.aligned.m8n8.x4.shared.b16 {%0,%1,%2,%3}, [%4];"
                 : "=r"(r[0]), "=r"(r[1]), "=r"(r[2]), "=r"(r[3]) : "r"(addr));
}
__device__ __forceinline__ void mma_bf16(float* d, const uint32_t* a, const uint32_t* b) {
    asm volatile(
        "mma.sync.aligned.m16n8k16.row.col.f32.bf16.bf16.f32 "
        "{%0,%1,%2,%3}, {%4,%5,%6,%7}, {%8,%9}, {%0,%1,%2,%3};"
        : "+f"(d[0]), "+f"(d[1]), "+f"(d[2]), "+f"(d[3])
        : "r"(a[0]), "r"(a[1]), "r"(a[2]), "r"(a[3]), "r"(b[0]), "r"(b[1]));
}
#define CP16(saddr, gptr) \
    asm volatile("cp.async.ca.shared.global [%0], [%1], 16;" :: "r"(saddr), "l"(gptr))
#define CP_COMMIT() asm volatile("cp.async.commit_group;" ::: "memory")
#define CP_WAIT0()  asm volatile("cp.async.wait_group 0;" ::: "memory")

// ---------------- kernel: normalize new_embeds + split to bf16 hi/lo ----------------
__global__ void normalize_split(const float* __restrict__ x) {
    int i = blockIdx.x, tid = threadIdx.x;           // 128 threads
    const float* xr = x + (size_t)i * DDIM;
    float s = 0.f;
    for (int d = tid; d < DDIM; d += 128) { float v = xr[d]; s += v * v; }
    for (int o = 16; o; o >>= 1) s += __shfl_down_sync(0xffffffffu, s, o);
    __shared__ float sh[4];
    if ((tid & 31) == 0) sh[tid >> 5] = s;
    __syncthreads();
    __shared__ float invs;
    if (tid == 0) invs = 1.0f / fmaxf(sqrtf(sh[0] + sh[1] + sh[2] + sh[3]), 1e-12f);
    __syncthreads();
    float iv = invs;
    for (int d = tid; d < DDIM; d += 128) {
        float v = xr[d] * iv;
        uint32_t b = __float_as_uint(v);
        float hi = __uint_as_float(b & 0xffff0000u);
        g_a1h[i * DDIM + d] = (unsigned short)(b >> 16);
        g_a1l[i * DDIM + d] = __bfloat16_as_ushort(__float2bfloat16_rn(v - hi));
    }
}

// ---------------- kernel: split new_logits to bf16 hi/lo ----------------
__global__ void split_logits(const float* __restrict__ x) {
    int idx = (blockIdx.x * blockDim.x + threadIdx.x) * 4;   // over 128*8192
    float4 v = *(const float4*)(x + idx);
    uint32_t bx = __float_as_uint(v.x), by = __float_as_uint(v.y);
    uint32_t bz = __float_as_uint(v.z), bw = __float_as_uint(v.w);
    uint2 hi;
    hi.x = __byte_perm(bx, by, 0x7632);
    hi.y = __byte_perm(bz, bw, 0x7632);
    *(uint2*)(g_a2h + idx) = hi;
    __nv_bfloat162 p0 = __floats2bfloat162_rn(v.x - __uint_as_float(bx & 0xffff0000u),
                                              v.y - __uint_as_float(by & 0xffff0000u));
    __nv_bfloat162 p1 = __floats2bfloat162_rn(v.z - __uint_as_float(bz & 0xffff0000u),
                                              v.w - __uint_as_float(bw & 0xffff0000u));
    uint2 lo; lo.x = *(uint32_t*)&p0; lo.y = *(uint32_t*)&p1;
    *(uint2*)(g_a2l + idx) = lo;
}

// ---------------- kernel: updated queue labels ----------------
__global__ void build_qlab(const int* __restrict__ ql, const int* __restrict__ labels,
                           const int* __restrict__ hdrp) {
    int j = blockIdx.x * blockDim.x + threadIdx.x;
    int hdr = *hdrp;
    int r = (j - hdr) & (NQ - 1);
    g_qlab[j] = (r < NROW) ? labels[r] : ql[j];
}

// ---------------- mma.sync bf16-split GEMM ----------------
// out[m, j] = sum_k A[m,k] * Brow(j)[k]; A pre-split bf16 hi/lo; B fp32 with row redirect.
// CTA tile 128x128, BK=32 bf16; 8 warps (4M x 2N), warp tile 32x64.
constexpr int BPAD = 80;                 // padded bytes per 32-bf16 row (conflict-free ldmatrix)
constexpr int O_AH = 0;
constexpr int O_AL = O_AH + 128 * BPAD;  // 10240
constexpr int O_BH = O_AL + 128 * BPAD;  // 20480
constexpr int O_BL = O_BH + 128 * BPAD;  // 30720
constexpr int STG  = O_BL + 128 * BPAD;  // 40960 per stage
constexpr int GEMM_SMEM = 2 * STG;       // 81920

__global__ __launch_bounds__(256, 2) void gemm_mma(
    const unsigned short* __restrict__ Ah,   // [128 x K] bf16 hi
    const unsigned short* __restrict__ Al,   // [128 x K] bf16 lo
    const float* __restrict__ Bq,            // [NQ x K]
    const float* __restrict__ Bold,          // [128 x K]
    const int* __restrict__ hdrp,
    float* __restrict__ out,                 // [128 x NQ]
    int K)
{
    extern __shared__ char smem[];
    const uint32_t sb = smem_u32(smem);
    const int tid = threadIdx.x, lane = tid & 31, wid = tid >> 5;
    const int wm = wid >> 1, wn = wid & 1;
    const int n0 = blockIdx.x * 128;
    const int nchunks = K >> 5;

    // B gmem pointer with circular-queue redirect
    const int rb = tid >> 1, seg = tid & 1;
    const int hdr = *hdrp;
    {
        // nothing
    }
    const int j = n0 + rb;
    const int r = (j - hdr) & (NQ - 1);
    const float* bptr = ((r < NROW) ? (Bold + (size_t)r * K) : (Bq + (size_t)j * K)) + seg * 16;

    // A cp.async assignment: thread covers 32B of one row per tile
    const int arow = tid >> 1;
    const int acol = (tid & 1) * 32;                 // byte offset in 64B of row data
    const char* gAh = (const char*)Ah + (size_t)arow * K * 2 + acol;
    const char* gAl = (const char*)Al + (size_t)arow * K * 2 + acol;
    const uint32_t sAh = sb + O_AH + arow * BPAD + acol;
    const uint32_t sAl = sb + O_AL + arow * BPAD + acol;
    const int bso = rb * BPAD + seg * 32;            // B smem store offset within tile

    // ldmatrix lane addressing
    const int g = lane >> 3, lr = lane & 7;
    const uint32_t aRowOff = (uint32_t)(wm * 32 + (g & 1) * 8 + lr) * BPAD + (g >> 1) * 16;
    const uint32_t bRowOff = (uint32_t)(wn * 64 + (g >> 1) * 8 + lr) * BPAD + (g & 1) * 16;

    float acc[2][8][4];
#pragma unroll
    for (int mt = 0; mt < 2; mt++)
#pragma unroll
        for (int nt = 0; nt < 8; nt++)
#pragma unroll
            for (int u = 0; u < 4; u++) acc[mt][nt][u] = 0.f;

    auto loadA = [&](int c, int st) {
        const char* s0 = gAh + (size_t)c * 64;
        const char* s1 = gAl + (size_t)c * 64;
        uint32_t d0 = sAh + st * STG;
        uint32_t d1 = sAl + st * STG;
        CP16(d0, s0); CP16(d0 + 16, s0 + 16);
        CP16(d1, s1); CP16(d1 + 16, s1 + 16);
        CP_COMMIT();
    };
    float4 f0, f1, f2, f3;
    auto loadB = [&](int c) {
        const float4* p = (const float4*)(bptr + (size_t)c * 32);
        f0 = __ldg(p); f1 = __ldg(p + 1); f2 = __ldg(p + 2); f3 = __ldg(p + 3);
    };
    auto storeB = [&](int st) {
        char* bh = smem + O_BH + st * STG + bso;
        char* bl = smem + O_BL + st * STG + bso;
        float4 xs[4] = {f0, f1, f2, f3};
#pragma unroll
        for (int u = 0; u < 2; u++) {
            float4 x = xs[2 * u], y = xs[2 * u + 1];
            uint32_t bxx = __float_as_uint(x.x), bxy = __float_as_uint(x.y);
            uint32_t bxz = __float_as_uint(x.z), bxw = __float_as_uint(x.w);
            uint32_t byx = __float_as_uint(y.x), byy = __float_as_uint(y.y);
            uint32_t byz = __float_as_uint(y.z), byw = __float_as_uint(y.w);
            uint4 hi;
            hi.x = __byte_perm(bxx, bxy, 0x7632);
            hi.y = __byte_perm(bxz, bxw, 0x7632);
            hi.z = __byte_perm(byx, byy, 0x7632);
            hi.w = __byte_perm(byz, byw, 0x7632);
            __nv_bfloat162 l0 = __floats2bfloat162_rn(x.x - __uint_as_float(bxx & 0xffff0000u),
                                                      x.y - __uint_as_float(bxy & 0xffff0000u));
            __nv_bfloat162 l1 = __floats2bfloat162_rn(x.z - __uint_as_float(bxz & 0xffff0000u),
                                                      x.w - __uint_as_float(bxw & 0xffff0000u));
            __nv_bfloat162 l2 = __floats2bfloat162_rn(y.x - __uint_as_float(byx & 0xffff0000u),
                                                      y.y - __uint_as_float(byy & 0xffff0000u));
            __nv_bfloat162 l3 = __floats2bfloat162_rn(y.z - __uint_as_float(byz & 0xffff0000u),
                                                      y.w - __uint_as_float(byw & 0xffff0000u));
            uint4 lo;
            lo.x = *(uint32_t*)&l0; lo.y = *(uint32_t*)&l1;
            lo.z = *(uint32_t*)&l2; lo.w = *(uint32_t*)&l3;
            *(uint4*)(bh + u * 16) = hi;
            *(uint4*)(bl + u * 16) = lo;
        }
    };

    auto compute = [&](int st) {
        const uint32_t bA0 = sb + O_AH + st * STG + aRowOff;
        const uint32_t bA1 = sb + O_AL + st * STG + aRowOff;
        const uint32_t bB0 = sb + O_BH + st * STG + bRowOff;
        const uint32_t bB1 = sb + O_BL + st * STG + bRowOff;
#pragma unroll
        for (int ks = 0; ks < 2; ks++) {
            uint32_t a0[2][4], a1[2][4], b[4][4];
            ldm4(a0[0], bA0 + ks * 32);
            ldm4(a0[1], bA0 + 16 * BPAD + ks * 32);
#pragma unroll
            for (int p = 0; p < 4; p++) ldm4(b[p], bB0 + p * 16 * BPAD + ks * 32);
#pragma unroll
            for (int mt = 0; mt < 2; mt++)
#pragma unroll
                for (int nt = 0; nt < 8; nt++)
                    mma_bf16(acc[mt][nt], a0[mt], &b[nt >> 1][(nt & 1) * 2]);
            ldm4(a1[0], bA1 + ks * 32);
            ldm4(a1[1], bA1 + 16 * BPAD + ks * 32);
#pragma unroll
            for (int mt = 0; mt < 2; mt++)
#pragma unroll
                for (int nt = 0; nt < 8; nt++)
                    mma_bf16(acc[mt][nt], a1[mt], &b[nt >> 1][(nt & 1) * 2]);
#pragma unroll
            for (int p = 0; p < 4; p++) ldm4(b[p], bB1 + p * 16 * BPAD + ks * 32);
#pragma unroll
            for (int mt = 0; mt < 2; mt++)
#pragma unroll
                for (int nt = 0; nt < 8; nt++)
                    mma_bf16(acc[mt][nt], a0[mt], &b[nt >> 1][(nt & 1) * 2]);
        }
    };

    // ---- pipeline ----
    loadA(0, 0);
    loadB(0);
    storeB(0);
    CP_WAIT0();
    __syncthreads();

    for (int c = 0; c < nchunks; c++) {
        const int st = c & 1;
        const bool more = (c + 1 < nchunks);
        if (more) { loadA(c + 1, st ^ 1); loadB(c + 1); }
        compute(st);
        if (more) { storeB(st ^ 1); CP_WAIT0(); }
        __syncthreads();
    }

    // ---- epilogue: register accumulators -> scores ----
    const int qr = lane >> 2, qc = (lane & 3) * 2;
#pragma unroll
    for (int mt = 0; mt < 2; mt++) {
        const int row = wm * 32 + mt * 16 + qr;
#pragma unroll
        for (int nt = 0; nt < 8; nt++) {
            const int col = n0 + wn * 64 + nt * 8 + qc;
            float2 v0; v0.x = acc[mt][nt][0]; v0.y = acc[mt][nt][1];
            float2 v1; v1.x = acc[mt][nt][2]; v1.y = acc[mt][nt][3];
            *(float2*)(out + (size_t)row * NQ + col) = v0;
            *(float2*)(out + (size_t)(row + 8) * NQ + col) = v1;
        }
    }
}

// ---------------- per-row reduction (two-pass over L2-resident scores) ----------------
__global__ __launch_bounds__(256) void row_reduce(
    const float* __restrict__ old_embeds, const float* __restrict__ feat_queue,
    const int* __restrict__ labels, const int* __restrict__ hdrp)
{
    const int i = blockIdx.x, tid = threadIdx.x;
    const int lbl = labels[i];
    const int hdr = *hdrp;
    const float* s1r = g_s1 + (size_t)i * NQ;
    const float* s2r = g_s2 + (size_t)i * NQ;
    const float* oei = old_embeds + (size_t)i * DDIM;

    float m1 = -INFINITY, m2 = -INFINITY;
    for (int jj = tid; jj < NQ; jj += 256) {
        m1 = fmaxf(m1, s1r[jj]);
        m2 = fmaxf(m2, s2r[jj]);
    }
    for (int o = 16; o; o >>= 1) {
        m1 = fmaxf(m1, __shfl_xor_sync(0xffffffffu, m1, o));
        m2 = fmaxf(m2, __shfl_xor_sync(0xffffffffu, m2, o));
    }
    __shared__ float shm1[8], shm2[8];
    if ((tid & 31) == 0) { shm1[tid >> 5] = m1; shm2[tid >> 5] = m2; }
    __syncthreads();
    float M1 = shm1[0], M2 = shm2[0];
    for (int w = 1; w < 8; w++) { M1 = fmaxf(M1, shm1[w]); M2 = fmaxf(M2, shm2[w]); }

    float l1 = 0.f, l2 = 0.f, sw = 0.f, s1w = 0.f, s2w = 0.f;
    int cnt = 0;
    for (int jj = tid; jj < NQ; jj += 256) {
        float v1 = s1r[jj], v2 = s2r[jj];
        l1 += expf(v1 - M1);
        l2 += expf(v2 - M2);
        if (g_qlab[jj] == lbl) {
            int r = (jj - hdr) & (NQ - 1);
            const float* frow = (r < NROW) ? (old_embeds + (size_t)r * DDIM)
                                           : (feat_queue + (size_t)jj * DDIM);
            float dot = 0.f;
#pragma unroll 8
            for (int d = 0; d < DDIM; d++) dot = fmaf(oei[d], frow[d], dot);
            float w = 0.5f * (dot + 1.0f);
            sw += w; s1w += w * v1; s2w += w * v2; cnt += 1;
        }
    }
    for (int o = 16; o; o >>= 1) {
        l1  += __shfl_down_sync(0xffffffffu, l1, o);
        l2  += __shfl_down_sync(0xffffffffu, l2, o);
        sw  += __shfl_down_sync(0xffffffffu, sw, o);
        s1w += __shfl_down_sync(0xffffffffu, s1w, o);
        s2w += __shfl_down_sync(0xffffffffu, s2w, o);
        cnt += __shfl_down_sync(0xffffffffu, cnt, o);
    }
    __shared__ float shl1[8], shl2[8], shsw[8], shs1[8], shs2[8];
    __shared__ int shc[8];
    if ((tid & 31) == 0) {
        int w = tid >> 5;
        shl1[w] = l1; shl2[w] = l2; shsw[w] = sw; shs1[w] = s1w; shs2[w] = s2w; shc[w] = cnt;
    }
    __syncthreads();
    if (tid == 0) {
        float L1 = 0, L2 = 0, SW = 0, S1 = 0, S2 = 0; int CN = 0;
        for (int w = 0; w < 8; w++) {
            L1 += shl1[w]; L2 += shl2[w]; SW += shsw[w];
            S1 += shs1[w]; S2 += shs2[w]; CN += shc[w];
        }
        float lse1 = M1 + logf(L1);
        float lse2 = M2 + logf(L2);
        float ic = 1.0f / (float)CN;
        g_terms[i]        = (S1 - lse1 * SW) * ic;
        g_terms[NROW + i] = (S2 - lse2 * SW) * ic;
    }
}

__global__ void finalize(float* __restrict__ out) {
    int tid = threadIdx.x;   // 128
    float t1 = g_terms[tid], t2 = g_terms[NROW + tid];
    for (int o = 16; o; o >>= 1) {
        t1 += __shfl_down_sync(0xffffffffu, t1, o);
        t2 += __shfl_down_sync(0xffffffffu, t2, o);
    }
    __shared__ float sh1[4], sh2[4];
    if ((tid & 31) == 0) { sh1[tid >> 5] = t1; sh2[tid >> 5] = t2; }
    __syncthreads();
    if (tid == 0) {
        out[0] = -(sh1[0] + sh1[1] + sh1[2] + sh1[3]) / (float)NROW;
        out[1] = -(sh2[0] + sh2[1] + sh2[2] + sh2[3]) / (float)NROW;
    }
}

// ---------------- launch ----------------
extern "C" void kernel_launch(void* const* d_in, const int* in_sizes, int n_in,
                              void* d_out, int out_size) {
    const float* old_embeds   = (const float*)d_in[0];
    const float* old_logits   = (const float*)d_in[1];
    const float* new_embeds   = (const float*)d_in[2];
    const float* new_logits   = (const float*)d_in[3];
    const int*   labels       = (const int*)d_in[4];
    const float* feat_queue   = (const float*)d_in[5];
    const float* logit_queue  = (const float*)d_in[6];
    const int*   queue_labels = (const int*)d_in[7];
    const int*   header       = (const int*)d_in[8];
    float* out = (float*)d_out;

    unsigned short *p_a1h, *p_a1l, *p_a2h, *p_a2l;
    float *p_s1, *p_s2;
    cudaGetSymbolAddress((void**)&p_a1h, g_a1h);
    cudaGetSymbolAddress((void**)&p_a1l, g_a1l);
    cudaGetSymbolAddress((void**)&p_a2h, g_a2h);
    cudaGetSymbolAddress((void**)&p_a2l, g_a2l);
    cudaGetSymbolAddress((void**)&p_s1, g_s1);
    cudaGetSymbolAddress((void**)&p_s2, g_s2);

    cudaFuncSetAttribute(gemm_mma, cudaFuncAttributeMaxDynamicSharedMemorySize, GEMM_SMEM);

    normalize_split<<<NROW, 128>>>(new_embeds);
    split_logits<<<(NROW * CDIM) / (256 * 4), 256>>>(new_logits);
    build_qlab<<<NQ / 256, 256>>>(queue_labels, labels, header);

    gemm_mma<<<NQ / 128, 256, GEMM_SMEM>>>(p_a1h, p_a1l, feat_queue, old_embeds,
                                           header, p_s1, DDIM);
    gemm_mma<<<NQ / 128, 256, GEMM_SMEM>>>(p_a2h, p_a2l, logit_queue, old_logits,
                                           header, p_s2, CDIM);

    row_reduce<<<NROW, 256>>>(old_embeds, feat_queue, labels, header);
    finalize<<<1, 128>>>(out);
}

// round 4
// speedup vs baseline: 2.6394x; 1.0040x over previous
#include <cuda_runtime.h>
#include <cuda_bf16.h>
#include <cstdint>
#include <math.h>

// Shapes (fixed)
constexpr int NROW = 128;
constexpr int DDIM = 512;
constexpr int CDIM = 8192;
constexpr int NQ   = 32768;

// ---------------- device scratch ----------------
__device__ __align__(16) float g_s1[(size_t)NROW * NQ];
__device__ __align__(16) float g_s2[(size_t)NROW * NQ];
__device__ __align__(16) unsigned short g_a1h[NROW * DDIM];
__device__ __align__(16) unsigned short g_a1l[NROW * DDIM];
__device__ __align__(16) unsigned short g_a2h[NROW * CDIM];
__device__ __align__(16) unsigned short g_a2l[NROW * CDIM];
__device__ int   g_qlab[NQ];
__device__ float g_part[256 * 8];     // per (row, half): m1,l1,m2,l2,sw,s1w,s2w,cnt

// ---------------- small helpers ----------------
__device__ __forceinline__ uint32_t smem_u32(const void* p) {
    uint32_t a;
    asm("{ .reg .u64 t; cvta.to.shared.u64 t, %1; cvt.u32.u64 %0, t; }" : "=r"(a) : "l"(p));
    return a;
}
__device__ __forceinline__ void ldm4(uint32_t* r, uint32_t addr) {
    asm volatile("ldmatrix.sync.aligned.m8n8.x4.shared.b16 {%0,%1,%2,%3}, [%4];"
                 : "=r"(r[0]), "=r"(r[1]), "=r"(r[2]), "=r"(r[3]) : "r"(addr));
}
__device__ __forceinline__ void mma_bf16(float* d, const uint32_t* a, const uint32_t* b) {
    asm volatile(
        "mma.sync.aligned.m16n8k16.row.col.f32.bf16.bf16.f32 "
        "{%0,%1,%2,%3}, {%4,%5,%6,%7}, {%8,%9}, {%0,%1,%2,%3};"
        : "+f"(d[0]), "+f"(d[1]), "+f"(d[2]), "+f"(d[3])
        : "r"(a[0]), "r"(a[1]), "r"(a[2]), "r"(a[3]), "r"(b[0]), "r"(b[1]));
}
#define CP16(saddr, gptr) \
    asm volatile("cp.async.ca.shared.global [%0], [%1], 16;" :: "r"(saddr), "l"(gptr))
#define CP_COMMIT() asm volatile("cp.async.commit_group;" ::: "memory")
#define CP_WAIT0()  asm volatile("cp.async.wait_group 0;" ::: "memory")

// ---------------- kernel: normalize new_embeds + split to bf16 hi/lo ----------------
__global__ void normalize_split(const float* __restrict__ x) {
    int i = blockIdx.x, tid = threadIdx.x;           // 128 threads
    const float* xr = x + (size_t)i * DDIM;
    float s = 0.f;
    for (int d = tid; d < DDIM; d += 128) { float v = xr[d]; s += v * v; }
    for (int o = 16; o; o >>= 1) s += __shfl_down_sync(0xffffffffu, s, o);
    __shared__ float sh[4];
    if ((tid & 31) == 0) sh[tid >> 5] = s;
    __syncthreads();
    __shared__ float invs;
    if (tid == 0) invs = 1.0f / fmaxf(sqrtf(sh[0] + sh[1] + sh[2] + sh[3]), 1e-12f);
    __syncthreads();
    float iv = invs;
    for (int d = tid; d < DDIM; d += 128) {
        float v = xr[d] * iv;
        uint32_t b = __float_as_uint(v);
        float hi = __uint_as_float(b & 0xffff0000u);
        g_a1h[i * DDIM + d] = (unsigned short)(b >> 16);
        g_a1l[i * DDIM + d] = __bfloat16_as_ushort(__float2bfloat16_rn(v - hi));
    }
}

// ---------------- kernel: split new_logits to bf16 hi/lo ----------------
__global__ void split_logits(const float* __restrict__ x) {
    int idx = (blockIdx.x * blockDim.x + threadIdx.x) * 4;   // over 128*8192
    float4 v = *(const float4*)(x + idx);
    uint32_t bx = __float_as_uint(v.x), by = __float_as_uint(v.y);
    uint32_t bz = __float_as_uint(v.z), bw = __float_as_uint(v.w);
    uint2 hi;
    hi.x = __byte_perm(bx, by, 0x7632);
    hi.y = __byte_perm(bz, bw, 0x7632);
    *(uint2*)(g_a2h + idx) = hi;
    __nv_bfloat162 p0 = __floats2bfloat162_rn(v.x - __uint_as_float(bx & 0xffff0000u),
                                              v.y - __uint_as_float(by & 0xffff0000u));
    __nv_bfloat162 p1 = __floats2bfloat162_rn(v.z - __uint_as_float(bz & 0xffff0000u),
                                              v.w - __uint_as_float(bw & 0xffff0000u));
    uint2 lo; lo.x = *(uint32_t*)&p0; lo.y = *(uint32_t*)&p1;
    *(uint2*)(g_a2l + idx) = lo;
}

// ---------------- kernel: updated queue labels ----------------
__global__ void build_qlab(const int* __restrict__ ql, const int* __restrict__ labels,
                           const int* __restrict__ hdrp) {
    int j = blockIdx.x * blockDim.x + threadIdx.x;
    int hdr = *hdrp;
    int r = (j - hdr) & (NQ - 1);
    g_qlab[j] = (r < NROW) ? labels[r] : ql[j];
}

// ---------------- mma.sync bf16-split GEMM ----------------
// CTA tile 128x128, BK=32; 8 warps (4M x 2N), warp tile 32x64.
// A pre-split bf16 hi/lo via cp.async (double-buffered).
// B fp32 via cp.async into staging (double-buffered), converted smem->smem to bf16 hi/lo.
constexpr int BPAD  = 80;      // bf16 tile row stride (32 bf16 + pad), conflict-free ldmatrix
constexpr int FPAD  = 144;     // fp32 staging row stride (32 fp32 + 16B pad)
constexpr int SZ_A  = 128 * BPAD;        // 10240 per A tile
constexpr int SZ_BF = 128 * FPAD;        // 18432 per fp32 stage
constexpr int O_AH  = 0;                 // [2 stages]
constexpr int O_AL  = 2 * SZ_A;          // 20480 [2 stages]
constexpr int O_BF  = 4 * SZ_A;          // 40960 [2 stages]
constexpr int O_BH  = O_BF + 2 * SZ_BF;  // 77824 [single]
constexpr int O_BL  = O_BH + SZ_A;       // 88064 [single]
constexpr int GEMM_SMEM = O_BL + SZ_A;   // 98304 (96KB) -> 2 CTAs/SM

__global__ __launch_bounds__(256, 2) void gemm_mma(
    const unsigned short* __restrict__ Ah,   // [128 x K] bf16 hi
    const unsigned short* __restrict__ Al,   // [128 x K] bf16 lo
    const float* __restrict__ Bq,            // [NQ x K]
    const float* __restrict__ Bold,          // [128 x K]
    const int* __restrict__ hdrp,
    float* __restrict__ out,                 // [128 x NQ]
    int K)
{
    extern __shared__ char smem[];
    const uint32_t sb = smem_u32(smem);
    const int tid = threadIdx.x, lane = tid & 31, wid = tid >> 5;
    const int wm = wid >> 1, wn = wid & 1;
    const int n0 = blockIdx.x * 128;
    const int nchunks = K >> 5;

    // B gmem row with circular-queue redirect; 2 threads per row, 64B each
    const int rb = tid >> 1, seg = tid & 1;
    const int hdr = *hdrp;
    const int j = n0 + rb;
    const int r = (j - hdr) & (NQ - 1);
    const char* gB = (const char*)(((r < NROW) ? (Bold + (size_t)r * K)
                                               : (Bq + (size_t)j * K)) + seg * 16);
    const uint32_t sBF = sb + O_BF + rb * FPAD + seg * 64;

    // A: 2 threads per row, 32B each, hi+lo
    const int arow = tid >> 1;
    const int acol = (tid & 1) * 32;
    const char* gAh = (const char*)Ah + (size_t)arow * K * 2 + acol;
    const char* gAl = (const char*)Al + (size_t)arow * K * 2 + acol;
    const uint32_t sA = sb + arow * BPAD + acol;

    // convert-side addressing (read fp32 stage, write bf16 tiles)
    const uint32_t cBH = sb + O_BH + rb * BPAD + seg * 32;
    const uint32_t cBL = sb + O_BL + rb * BPAD + seg * 32;

    // ldmatrix lane addressing
    const int g = lane >> 3, lr = lane & 7;
    const uint32_t aRowOff = (uint32_t)(wm * 32 + (g & 1) * 8 + lr) * BPAD + (g >> 1) * 16;
    const uint32_t bRowOff = (uint32_t)(wn * 64 + (g >> 1) * 8 + lr) * BPAD + (g & 1) * 16;
    const uint32_t bBH = sb + O_BH + bRowOff;
    const uint32_t bBL = sb + O_BL + bRowOff;

    float acc[2][8][4];
#pragma unroll
    for (int mt = 0; mt < 2; mt++)
#pragma unroll
        for (int nt = 0; nt < 8; nt++)
#pragma unroll
            for (int u = 0; u < 4; u++) acc[mt][nt][u] = 0.f;

    auto cpChunk = [&](int c, int st) {
        // A hi/lo: 32B each
        const char* s0 = gAh + (size_t)c * 64;
        const char* s1 = gAl + (size_t)c * 64;
        uint32_t d0 = sA + O_AH + st * SZ_A;
        uint32_t d1 = sA + O_AL + st * SZ_A;
        CP16(d0, s0); CP16(d0 + 16, s0 + 16);
        CP16(d1, s1); CP16(d1 + 16, s1 + 16);
        // B fp32: 64B
        const char* sB = gB + (size_t)c * 128;
        uint32_t dB = sBF + st * SZ_BF;
#pragma unroll
        for (int u = 0; u < 4; u++) CP16(dB + u * 16, sB + u * 16);
        CP_COMMIT();
    };

    auto convertB = [&](int st) {
        const float4* src = (const float4*)(smem + O_BF + st * SZ_BF + rb * FPAD + seg * 64);
#pragma unroll
        for (int h = 0; h < 2; h++) {           // two 8-float groups
            float4 x = src[2 * h], y = src[2 * h + 1];
            uint32_t bxx = __float_as_uint(x.x), bxy = __float_as_uint(x.y);
            uint32_t bxz = __float_as_uint(x.z), bxw = __float_as_uint(x.w);
            uint32_t byx = __float_as_uint(y.x), byy = __float_as_uint(y.y);
            uint32_t byz = __float_as_uint(y.z), byw = __float_as_uint(y.w);
            uint4 hi;
            hi.x = __byte_perm(bxx, bxy, 0x7632);
            hi.y = __byte_perm(bxz, bxw, 0x7632);
            hi.z = __byte_perm(byx, byy, 0x7632);
            hi.w = __byte_perm(byz, byw, 0x7632);
            __nv_bfloat162 l0 = __floats2bfloat162_rn(x.x - __uint_as_float(bxx & 0xffff0000u),
                                                      x.y - __uint_as_float(bxy & 0xffff0000u));
            __nv_bfloat162 l1 = __floats2bfloat162_rn(x.z - __uint_as_float(bxz & 0xffff0000u),
                                                      x.w - __uint_as_float(bxw & 0xffff0000u));
            __nv_bfloat162 l2 = __floats2bfloat162_rn(y.x - __uint_as_float(byx & 0xffff0000u),
                                                      y.y - __uint_as_float(byy & 0xffff0000u));
            __nv_bfloat162 l3 = __floats2bfloat162_rn(y.z - __uint_as_float(byz & 0xffff0000u),
                                                      y.w - __uint_as_float(byw & 0xffff0000u));
            uint4 lo;
            lo.x = *(uint32_t*)&l0; lo.y = *(uint32_t*)&l1;
            lo.z = *(uint32_t*)&l2; lo.w = *(uint32_t*)&l3;
            *(uint4*)((char*)smem + (cBH - sb) + h * 16) = hi;
            *(uint4*)((char*)smem + (cBL - sb) + h * 16) = lo;
        }
    };

    auto compute = [&](int st) {
        const uint32_t bA0 = sb + O_AH + st * SZ_A + aRowOff;
        const uint32_t bA1 = sb + O_AL + st * SZ_A + aRowOff;
#pragma unroll
        for (int ks = 0; ks < 2; ks++) {
            uint32_t a0[2][4], a1[2][4], bh[4][4], bl[4][4];
            ldm4(a0[0], bA0 + ks * 32);
            ldm4(a0[1], bA0 + 16 * BPAD + ks * 32);
#pragma unroll
            for (int p = 0; p < 4; p++) ldm4(bh[p], bBH + p * 16 * BPAD + ks * 32);
            // issue next loads under the first MMA block
            ldm4(a1[0], bA1 + ks * 32);
            ldm4(a1[1], bA1 + 16 * BPAD + ks * 32);
#pragma unroll
            for (int mt = 0; mt < 2; mt++)
#pragma unroll
                for (int nt = 0; nt < 8; nt++)
                    mma_bf16(acc[mt][nt], a0[mt], &bh[nt >> 1][(nt & 1) * 2]);
#pragma unroll
            for (int p = 0; p < 4; p++) ldm4(bl[p], bBL + p * 16 * BPAD + ks * 32);
#pragma unroll
            for (int mt = 0; mt < 2; mt++)
#pragma unroll
                for (int nt = 0; nt < 8; nt++)
                    mma_bf16(acc[mt][nt], a1[mt], &bh[nt >> 1][(nt & 1) * 2]);
#pragma unroll
            for (int mt = 0; mt < 2; mt++)
#pragma unroll
                for (int nt = 0; nt < 8; nt++)
                    mma_bf16(acc[mt][nt], a0[mt], &bl[nt >> 1][(nt & 1) * 2]);
        }
    };

    // ---- pipeline ----
    cpChunk(0, 0);
    CP_WAIT0();
    __syncthreads();

    for (int c = 0; c < nchunks; c++) {
        const int st = c & 1;
        if (c + 1 < nchunks) cpChunk(c + 1, st ^ 1);
        convertB(st);
        __syncthreads();          // BH/BL ready
        compute(st);
        CP_WAIT0();               // next chunk's DMA landed (hidden by compute)
        __syncthreads();          // BH/BL free for next convert; stages flip
    }

    // ---- epilogue ----
    const int qr = lane >> 2, qc = (lane & 3) * 2;
#pragma unroll
    for (int mt = 0; mt < 2; mt++) {
        const int row = wm * 32 + mt * 16 + qr;
#pragma unroll
        for (int nt = 0; nt < 8; nt++) {
            const int col = n0 + wn * 64 + nt * 8 + qc;
            float2 v0; v0.x = acc[mt][nt][0]; v0.y = acc[mt][nt][1];
            float2 v1; v1.x = acc[mt][nt][2]; v1.y = acc[mt][nt][3];
            *(float2*)(out + (size_t)row * NQ + col) = v0;
            *(float2*)(out + (size_t)(row + 8) * NQ + col) = v1;
        }
    }
}

// ---------------- per-row reduction: 2 blocks per row (half-Q each) ----------------
__global__ __launch_bounds__(256) void row_reduce(
    const float* __restrict__ old_embeds, const float* __restrict__ feat_queue,
    const int* __restrict__ labels, const int* __restrict__ hdrp)
{
    const int i = blockIdx.x >> 1, half = blockIdx.x & 1, tid = threadIdx.x;
    const int lbl = labels[i];
    const int hdr = *hdrp;
    const int j0 = half * (NQ / 2);
    const float4* s1r = (const float4*)(g_s1 + (size_t)i * NQ + j0);
    const float4* s2r = (const float4*)(g_s2 + (size_t)i * NQ + j0);
    const int4*   ql4 = (const int4*)(g_qlab + j0);
    const float* oei = old_embeds + (size_t)i * DDIM;
    constexpr int NV = (NQ / 2) / 4;   // float4 count per half = 4096

    float m1 = -INFINITY, m2 = -INFINITY;
    for (int v = tid; v < NV; v += 256) {
        float4 a = s1r[v], b = s2r[v];
        m1 = fmaxf(fmaxf(fmaxf(m1, a.x), fmaxf(a.y, a.z)), a.w);
        m2 = fmaxf(fmaxf(fmaxf(m2, b.x), fmaxf(b.y, b.z)), b.w);
    }
    for (int o = 16; o; o >>= 1) {
        m1 = fmaxf(m1, __shfl_xor_sync(0xffffffffu, m1, o));
        m2 = fmaxf(m2, __shfl_xor_sync(0xffffffffu, m2, o));
    }
    __shared__ float shm1[8], shm2[8];
    if ((tid & 31) == 0) { shm1[tid >> 5] = m1; shm2[tid >> 5] = m2; }
    __syncthreads();
    float M1 = shm1[0], M2 = shm2[0];
    for (int w = 1; w < 8; w++) { M1 = fmaxf(M1, shm1[w]); M2 = fmaxf(M2, shm2[w]); }

    float l1 = 0.f, l2 = 0.f, sw = 0.f, s1w = 0.f, s2w = 0.f, cnt = 0.f;
    for (int v = tid; v < NV; v += 256) {
        float4 a = s1r[v], b = s2r[v];
        l1 += __expf(a.x - M1) + __expf(a.y - M1) + __expf(a.z - M1) + __expf(a.w - M1);
        l2 += __expf(b.x - M2) + __expf(b.y - M2) + __expf(b.z - M2) + __expf(b.w - M2);
        int4 q = ql4[v];
        if (q.x == lbl || q.y == lbl || q.z == lbl || q.w == lbl) {
            const float va[4] = {a.x, a.y, a.z, a.w};
            const float vb[4] = {b.x, b.y, b.z, b.w};
            const int   qq[4] = {q.x, q.y, q.z, q.w};
#pragma unroll
            for (int e = 0; e < 4; e++) {
                if (qq[e] != lbl) continue;
                int jj = j0 + v * 4 + e;
                int r = (jj - hdr) & (NQ - 1);
                const float* frow = (r < NROW) ? (old_embeds + (size_t)r * DDIM)
                                               : (feat_queue + (size_t)jj * DDIM);
                float dot = 0.f;
#pragma unroll 8
                for (int d = 0; d < DDIM; d++) dot = fmaf(oei[d], frow[d], dot);
                float w = 0.5f * (dot + 1.0f);
                sw += w; s1w += w * va[e]; s2w += w * vb[e]; cnt += 1.f;
            }
        }
    }
    for (int o = 16; o; o >>= 1) {
        l1  += __shfl_down_sync(0xffffffffu, l1, o);
        l2  += __shfl_down_sync(0xffffffffu, l2, o);
        sw  += __shfl_down_sync(0xffffffffu, sw, o);
        s1w += __shfl_down_sync(0xffffffffu, s1w, o);
        s2w += __shfl_down_sync(0xffffffffu, s2w, o);
        cnt += __shfl_down_sync(0xffffffffu, cnt, o);
    }
    __shared__ float shl1[8], shl2[8], shsw[8], shs1[8], shs2[8], shc[8];
    if ((tid & 31) == 0) {
        int w = tid >> 5;
        shl1[w] = l1; shl2[w] = l2; shsw[w] = sw; shs1[w] = s1w; shs2[w] = s2w; shc[w] = cnt;
    }
    __syncthreads();
    if (tid == 0) {
        float L1 = 0, L2 = 0, SW = 0, S1 = 0, S2 = 0, CN = 0;
        for (int w = 0; w < 8; w++) {
            L1 += shl1[w]; L2 += shl2[w]; SW += shsw[w];
            S1 += shs1[w]; S2 += shs2[w]; CN += shc[w];
        }
        float* p = g_part + blockIdx.x * 8;
        p[0] = M1; p[1] = L1; p[2] = M2; p[3] = L2;
        p[4] = SW; p[5] = S1; p[6] = S2; p[7] = CN;
    }
}

// ---------------- finalize: merge halves, compute both losses ----------------
__global__ void finalize(float* __restrict__ out) {
    int tid = threadIdx.x;   // 128 threads, one row each
    const float* pa = g_part + (2 * tid) * 8;
    const float* pb = g_part + (2 * tid + 1) * 8;
    float M1 = fmaxf(pa[0], pb[0]);
    float L1 = pa[1] * __expf(pa[0] - M1) + pb[1] * __expf(pb[0] - M1);
    float M2 = fmaxf(pa[2], pb[2]);
    float L2 = pa[3] * __expf(pa[2] - M2) + pb[3] * __expf(pb[2] - M2);
    float SW = pa[4] + pb[4];
    float S1 = pa[5] + pb[5];
    float S2 = pa[6] + pb[6];
    float CN = pa[7] + pb[7];
    float lse1 = M1 + logf(L1);
    float lse2 = M2 + logf(L2);
    float ic = 1.0f / CN;
    float t1 = (S1 - lse1 * SW) * ic;
    float t2 = (S2 - lse2 * SW) * ic;
    for (int o = 16; o; o >>= 1) {
        t1 += __shfl_down_sync(0xffffffffu, t1, o);
        t2 += __shfl_down_sync(0xffffffffu, t2, o);
    }
    __shared__ float sh1[4], sh2[4];
    if ((tid & 31) == 0) { sh1[tid >> 5] = t1; sh2[tid >> 5] = t2; }
    __syncthreads();
    if (tid == 0) {
        out[0] = -(sh1[0] + sh1[1] + sh1[2] + sh1[3]) / (float)NROW;
        out[1] = -(sh2[0] + sh2[1] + sh2[2] + sh2[3]) / (float)NROW;
    }
}

// ---------------- launch ----------------
extern "C" void kernel_launch(void* const* d_in, const int* in_sizes, int n_in,
                              void* d_out, int out_size) {
    const float* old_embeds   = (const float*)d_in[0];
    const float* old_logits   = (const float*)d_in[1];
    const float* new_embeds   = (const float*)d_in[2];
    const float* new_logits   = (const float*)d_in[3];
    const int*   labels       = (const int*)d_in[4];
    const float* feat_queue   = (const float*)d_in[5];
    const float* logit_queue  = (const float*)d_in[6];
    const int*   queue_labels = (const int*)d_in[7];
    const int*   header       = (const int*)d_in[8];
    float* out = (float*)d_out;

    unsigned short *p_a1h, *p_a1l, *p_a2h, *p_a2l;
    float *p_s1, *p_s2;
    cudaGetSymbolAddress((void**)&p_a1h, g_a1h);
    cudaGetSymbolAddress((void**)&p_a1l, g_a1l);
    cudaGetSymbolAddress((void**)&p_a2h, g_a2h);
    cudaGetSymbolAddress((void**)&p_a2l, g_a2l);
    cudaGetSymbolAddress((void**)&p_s1, g_s1);
    cudaGetSymbolAddress((void**)&p_s2, g_s2);

    cudaFuncSetAttribute(gemm_mma, cudaFuncAttributeMaxDynamicSharedMemorySize, GEMM_SMEM);

    normalize_split<<<NROW, 128>>>(new_embeds);
    split_logits<<<(NROW * CDIM) / (256 * 4), 256>>>(new_logits);
    build_qlab<<<NQ / 256, 256>>>(queue_labels, labels, header);

    gemm_mma<<<NQ / 128, 256, GEMM_SMEM>>>(p_a1h, p_a1l, feat_queue, old_embeds,
                                           header, p_s1, DDIM);
    gemm_mma<<<NQ / 128, 256, GEMM_SMEM>>>(p_a2h, p_a2l, logit_queue, old_logits,
                                           header, p_s2, CDIM);

    row_reduce<<<2 * NROW, 256>>>(old_embeds, feat_queue, labels, header);
    finalize<<<1, 128>>>(out);
}